// round 15
// baseline (speedup 1.0000x reference)
#include <cuda_runtime.h>
#include <cuda_bf16.h>
#include <cstdint>

#define NNODES 100000
#define HD 128
#define ROW 640      // 5*HD
#define LMAX 262144
#define SBLK 98      // ceil(100000/1024) scan blocks per side

// scratch (self-cleaning across graph replays; zero-init at load)
__device__ int    g_cnt [2 * NNODES];  // k_count +, scanA reads then zeroes
__device__ int    g_cnt2[2 * NNODES];  // snapshot (scanA)
__device__ int    g_off [2 * NNODES];
__device__ int    g_cur [2 * NNODES];
__device__ float  g_inv [2 * NNODES];
__device__ float4 g_hdr [2 * NNODES];  // {bits(off), bits(cnt), inv, 0} (scanC)
__device__ int    g_bsum[2 * SBLK];
__device__ int    g_boff[2 * SBLK];
// sorted per-(side,position) event records: 2 float4s each.
// rec[2p+0] = {bits(e), bits(other), s0, c1}   rec[2p+1] = {cm, cb, x, pad}
__device__ float4 g_rec[4 * LMAX];

// ---------------------------------------------------------------------------
// fast cos: Cody-Waite FMA reduction + cephes minimax polys. |x|<=~1000 here.
// ---------------------------------------------------------------------------
__device__ __forceinline__ float fast_cos(float x) {
    float j = rintf(x * 0.63661977236758134f);
    int   q = (int)j;
    float r = fmaf(j, -1.5707963705062866f, x);
    r = fmaf(j, 4.3711390e-8f, r);
    float r2 = r * r;
    float ps = fmaf(r2, -1.9515295891e-4f, 8.3321608736e-3f);
    ps = fmaf(r2, ps, -1.6666654611e-1f);
    float s  = fmaf(r * r2, ps, r);
    float pc = fmaf(r2, 2.443315711809948e-5f, -1.388731625493765e-3f);
    pc = fmaf(r2, pc, 4.166664568298827e-2f);
    pc = fmaf(r2, pc, -0.5f);
    float c  = fmaf(r2, pc, 1.0f);
    float v = (q & 1) ? s : c;
    if ((q + 1) & 2) v = -v;
    return v;
}

// ---------------------------------------------------------------------------
__global__ void k_count(const int* __restrict__ src, const int* __restrict__ dst,
                        int L) {
    int i = blockIdx.x * blockDim.x + threadIdx.x;
    if (i >= L) return;
    atomicAdd(&g_cnt[src[i]], 1);
    atomicAdd(&g_cnt[NNODES + dst[i]], 1);
}

// ---------------------------------------------------------------------------
// scanA: coalesced block-local exclusive scan (1024/block), per side.
// ---------------------------------------------------------------------------
__global__ void __launch_bounds__(1024)
k_scanA() {
    __shared__ int sh[1024];
    int side = blockIdx.y;
    int gid  = blockIdx.x * 1024 + threadIdx.x;
    int idx  = side * NNODES + gid;
    bool ok  = gid < NNODES;
    int c = ok ? g_cnt[idx] : 0;
    sh[threadIdx.x] = c;
    __syncthreads();
    for (int d = 1; d < 1024; d <<= 1) {
        int t = (threadIdx.x >= d) ? sh[threadIdx.x - d] : 0;
        __syncthreads();
        sh[threadIdx.x] += t;
        __syncthreads();
    }
    if (ok) {
        g_off [idx] = sh[threadIdx.x] - c;   // exclusive within block
        g_cnt2[idx] = c;
        g_inv [idx] = 1.0f / (float)max(c, 1);
        g_cur [idx] = 0;
        g_cnt [idx] = 0;                     // self-clean for next replay
    }
    if (threadIdx.x == 1023) g_bsum[side * SBLK + blockIdx.x] = sh[1023];
}

// scanB: one block scans the 98 block sums of each side (exclusive).
__global__ void k_scanB() {
    __shared__ int sh[2][128];
    int tid  = threadIdx.x;          // 256 threads
    int side = tid >> 7, j = tid & 127;
    int v = (j < SBLK) ? g_bsum[side * SBLK + j] : 0;
    sh[side][j] = v;
    __syncthreads();
    for (int d = 1; d < 128; d <<= 1) {
        int t = (j >= d) ? sh[side][j - d] : 0;
        __syncthreads();
        sh[side][j] += t;
        __syncthreads();
    }
    if (j < SBLK) g_boff[side * SBLK + j] = sh[side][j] - v;
}

// scanC: add block offsets (coalesced) + emit packed per-slot header.
__global__ void __launch_bounds__(1024)
k_scanC() {
    int side = blockIdx.y;
    int gid  = blockIdx.x * 1024 + threadIdx.x;
    if (gid >= NNODES) return;
    int idx = side * NNODES + gid;
    int off = g_off[idx] + g_boff[side * SBLK + blockIdx.x];
    g_off[idx] = off;
    g_hdr[idx] = make_float4(__int_as_float(off), __int_as_float(g_cnt2[idx]),
                             g_inv[idx], 0.0f);
}

// ---------------------------------------------------------------------------
// counting-sort fill: write fully-precomputed records at sorted positions.
// ---------------------------------------------------------------------------
__global__ void k_fill(const int* __restrict__ type, const int* __restrict__ src,
                       const float* __restrict__ sm, const int* __restrict__ dst,
                       const float* __restrict__ dm, const float* __restrict__ em,
                       const float* __restrict__ ts, const float* __restrict__ lu,
                       int L) {
    int i = blockIdx.x * blockDim.x + threadIdx.x;
    if (i >= L) return;
    int   s   = src[i], d = dst[i];
    float smv = sm[i], dmv = dm[i], emv = em[i], t = ts[i];
    float ty  = (float)type[i];
    float lus = __ldg(lu + s), lud = __ldg(lu + d);

    // src side: message scale cb = event_mask
    int p = atomicAdd(&g_cur[s], 1) + g_off[s];
    g_rec[2 * p]     = make_float4(__int_as_float(i), __int_as_float(d),
                                   ty * emv, smv * emv);
    g_rec[2 * p + 1] = make_float4(dmv * emv, emv, t - lus * dmv, 0.0f);

    // dst side: cb = dst_mask (faithful: lu*dst_mask both sides)
    p = atomicAdd(&g_cur[NNODES + d], 1) + g_off[NNODES + d] + LMAX;
    g_rec[2 * p]     = make_float4(__int_as_float(i), __int_as_float(s),
                                   ty * dmv, dmv * dmv);
    g_rec[2 * p + 1] = make_float4(smv * dmv, dmv, t - lud * dmv, 0.0f);
}

// ---------------------------------------------------------------------------
// paired gather: one warp per NODE, handling both sides (src slot n, dst slot
// NNODES+n). Two independent record chains interleave -> 2x per-warp MLP;
// Mn / w / b loaded once. Lane l owns h = 4l..4l+3. Rows written exactly once.
// ---------------------------------------------------------------------------
__global__ void __launch_bounds__(256)
k_gather(const float4* __restrict__ E4, const float4* __restrict__ M4,
         const float4* __restrict__ W4, const float4* __restrict__ B4,
         float4* __restrict__ out4) {
    int n    = (blockIdx.x * blockDim.x + threadIdx.x) >> 5;
    int lane = threadIdx.x & 31;
    if (n >= NNODES) return;

    float4 hs = __ldg(&g_hdr[n]);
    float4 hd = __ldg(&g_hdr[NNODES + n]);
    int   off_s = __float_as_int(hs.x);
    int   cnt_s = __float_as_int(hs.y);
    float inv_s = hs.z;
    int   off_d = __float_as_int(hd.x) + LMAX;
    int   cnt_d = __float_as_int(hd.y);
    float inv_d = hd.z;
    float4 wv = __ldg(W4 + lane), bv = __ldg(B4 + lane);

    float  a0s = 0.f, a1s = 0.f, a0d = 0.f, a1d = 0.f;
    float4 a2s = make_float4(0,0,0,0), a3s = a2s, a4s = a2s;
    float4 a2d = a2s, a3d = a2s, a4d = a2s;

    float4 ras = make_float4(0,0,0,0), rbs = ras, rad = ras, rbd = ras;
    if (cnt_s > 0) { ras = __ldg(g_rec + 2*off_s); rbs = __ldg(g_rec + 2*off_s + 1); }
    if (cnt_d > 0) { rad = __ldg(g_rec + 2*off_d); rbd = __ldg(g_rec + 2*off_d + 1); }

    int cmax = max(cnt_s, cnt_d);
    for (int j = 0; j < cmax; j++) {
        // prefetch next records (both sides, independent)
        float4 ras_n = ras, rbs_n = rbs, rad_n = rad, rbd_n = rbd;
        if (j + 1 < cnt_s) {
            ras_n = __ldg(g_rec + 2*(off_s + j + 1));
            rbs_n = __ldg(g_rec + 2*(off_s + j + 1) + 1);
        }
        if (j + 1 < cnt_d) {
            rad_n = __ldg(g_rec + 2*(off_d + j + 1));
            rbd_n = __ldg(g_rec + 2*(off_d + j + 1) + 1);
        }
        // issue all gathers before any math
        float4 Evs, Mvs, Evd, Mvd;
        bool ps = j < cnt_s, pd = j < cnt_d;
        if (ps) {
            Evs = __ldcs(E4 + (size_t)__float_as_int(ras.x) * 32 + lane);
            Mvs = __ldg (M4 + (size_t)__float_as_int(ras.y) * 32 + lane);
        }
        if (pd) {
            Evd = __ldcs(E4 + (size_t)__float_as_int(rad.x) * 32 + lane);
            Mvd = __ldg (M4 + (size_t)__float_as_int(rad.y) * 32 + lane);
        }
        if (ps) {
            float cm = rbs.x, cb = rbs.y, x = rbs.z;
            a0s += ras.z;  a1s += ras.w;
            a2s.x = fmaf(Mvs.x, cm, a2s.x); a2s.y = fmaf(Mvs.y, cm, a2s.y);
            a2s.z = fmaf(Mvs.z, cm, a2s.z); a2s.w = fmaf(Mvs.w, cm, a2s.w);
            a3s.x = fmaf(fast_cos(fmaf(x, wv.x, bv.x)), cb, a3s.x);
            a3s.y = fmaf(fast_cos(fmaf(x, wv.y, bv.y)), cb, a3s.y);
            a3s.z = fmaf(fast_cos(fmaf(x, wv.z, bv.z)), cb, a3s.z);
            a3s.w = fmaf(fast_cos(fmaf(x, wv.w, bv.w)), cb, a3s.w);
            a4s.x = fmaf(Evs.x, cb, a4s.x); a4s.y = fmaf(Evs.y, cb, a4s.y);
            a4s.z = fmaf(Evs.z, cb, a4s.z); a4s.w = fmaf(Evs.w, cb, a4s.w);
        }
        if (pd) {
            float cm = rbd.x, cb = rbd.y, x = rbd.z;
            a0d += rad.z;  a1d += rad.w;
            a2d.x = fmaf(Mvd.x, cm, a2d.x); a2d.y = fmaf(Mvd.y, cm, a2d.y);
            a2d.z = fmaf(Mvd.z, cm, a2d.z); a2d.w = fmaf(Mvd.w, cm, a2d.w);
            a3d.x = fmaf(fast_cos(fmaf(x, wv.x, bv.x)), cb, a3d.x);
            a3d.y = fmaf(fast_cos(fmaf(x, wv.y, bv.y)), cb, a3d.y);
            a3d.z = fmaf(fast_cos(fmaf(x, wv.z, bv.z)), cb, a3d.z);
            a3d.w = fmaf(fast_cos(fmaf(x, wv.w, bv.w)), cb, a3d.w);
            a4d.x = fmaf(Evd.x, cb, a4d.x); a4d.y = fmaf(Evd.y, cb, a4d.y);
            a4d.z = fmaf(Evd.z, cb, a4d.z); a4d.w = fmaf(Evd.w, cb, a4d.w);
        }
        ras = ras_n; rbs = rbs_n; rad = rad_n; rbd = rbd_n;
    }

    float4 Mn = __ldg(M4 + (size_t)n * 32 + lane);
    {
        float b0 = a0s * inv_s, b1 = a1s * inv_s;
        float4* o = out4 + (size_t)n * 160;
        __stcs(o + lane,       make_float4(b0, b0, b0, b0));
        __stcs(o + 32 + lane,  make_float4(Mn.x*b1, Mn.y*b1, Mn.z*b1, Mn.w*b1));
        __stcs(o + 64 + lane,  make_float4(a2s.x*inv_s, a2s.y*inv_s, a2s.z*inv_s, a2s.w*inv_s));
        __stcs(o + 96 + lane,  make_float4(a3s.x*inv_s, a3s.y*inv_s, a3s.z*inv_s, a3s.w*inv_s));
        __stcs(o + 128 + lane, make_float4(a4s.x*inv_s, a4s.y*inv_s, a4s.z*inv_s, a4s.w*inv_s));
    }
    {
        float b0 = a0d * inv_d, b1 = a1d * inv_d;
        float4* o = out4 + (size_t)(NNODES + n) * 160;
        __stcs(o + lane,       make_float4(b0, b0, b0, b0));
        __stcs(o + 32 + lane,  make_float4(Mn.x*b1, Mn.y*b1, Mn.z*b1, Mn.w*b1));
        __stcs(o + 64 + lane,  make_float4(a2d.x*inv_d, a2d.y*inv_d, a2d.z*inv_d, a2d.w*inv_d));
        __stcs(o + 96 + lane,  make_float4(a3d.x*inv_d, a3d.y*inv_d, a3d.z*inv_d, a3d.w*inv_d));
        __stcs(o + 128 + lane, make_float4(a4d.x*inv_d, a4d.y*inv_d, a4d.z*inv_d, a4d.w*inv_d));
    }
}

// ---------------------------------------------------------------------------
extern "C" void kernel_launch(void* const* d_in, const int* in_sizes, int n_in,
                              void* d_out, int out_size) {
    const int*   type = (const int*)  d_in[0];
    const int*   src  = (const int*)  d_in[1];
    const float* smk  = (const float*)d_in[2];
    const int*   dst  = (const int*)  d_in[3];
    const float* dmk  = (const float*)d_in[4];
    const float* E    = (const float*)d_in[5];
    const float* em   = (const float*)d_in[6];
    const float* ts   = (const float*)d_in[7];
    const float* mem  = (const float*)d_in[8];
    const float* lu   = (const float*)d_in[9];
    const float* w    = (const float*)d_in[10];
    const float* b    = (const float*)d_in[11];
    float* out = (float*)d_out;
    int L = in_sizes[0];
    if (L > LMAX) L = LMAX;

    dim3 sgrid(SBLK, 2);
    k_count<<<(L + 255) / 256, 256>>>(src, dst, L);
    k_scanA<<<sgrid, 1024>>>();
    k_scanB<<<1, 256>>>();
    k_scanC<<<sgrid, 1024>>>();
    k_fill <<<(L + 255) / 256, 256>>>(type, src, smk, dst, dmk, em, ts, lu, L);

    int warps = NNODES;   // one warp per node (both sides)
    k_gather<<<(warps * 32 + 255) / 256, 256>>>(
        (const float4*)E, (const float4*)mem, (const float4*)w,
        (const float4*)b, (float4*)out);
}

// round 16
// speedup vs baseline: 1.0592x; 1.0592x over previous
#include <cuda_runtime.h>
#include <cuda_bf16.h>
#include <cstdint>

#define NNODES 100000
#define HD 128
#define ROW 640      // 5*HD
#define LMAX 262144
#define SBLK 98      // ceil(100000/1024) scan blocks per side

// scratch (self-cleaning across graph replays; zero-init at load)
__device__ int    g_cnt [2 * NNODES];  // k_count +, scanA reads then zeroes
__device__ int    g_cnt2[2 * NNODES];  // snapshot (scanA)
__device__ int    g_off [2 * NNODES];
__device__ int    g_cur [2 * NNODES];
__device__ float  g_inv [2 * NNODES];
__device__ float4 g_hdr [2 * NNODES];  // {bits(off), bits(cnt), inv, 0} (scanC)
__device__ int    g_bsum[2 * SBLK];
__device__ int    g_boff[2 * SBLK];
// sorted per-(side,position) event records: 2 float4s each.
// rec[2p+0] = {bits(e), bits(other), s0, c1}   rec[2p+1] = {cm, cb, x, pad}
__device__ float4 g_rec[4 * LMAX];

// ---------------------------------------------------------------------------
// fast cos: Cody-Waite FMA reduction + cephes minimax polys. |x|<=~1000 here.
// ---------------------------------------------------------------------------
__device__ __forceinline__ float fast_cos(float x) {
    float j = rintf(x * 0.63661977236758134f);
    int   q = (int)j;
    float r = fmaf(j, -1.5707963705062866f, x);
    r = fmaf(j, 4.3711390e-8f, r);
    float r2 = r * r;
    float ps = fmaf(r2, -1.9515295891e-4f, 8.3321608736e-3f);
    ps = fmaf(r2, ps, -1.6666654611e-1f);
    float s  = fmaf(r * r2, ps, r);
    float pc = fmaf(r2, 2.443315711809948e-5f, -1.388731625493765e-3f);
    pc = fmaf(r2, pc, 4.166664568298827e-2f);
    pc = fmaf(r2, pc, -0.5f);
    float c  = fmaf(r2, pc, 1.0f);
    float v = (q & 1) ? s : c;
    if ((q + 1) & 2) v = -v;
    return v;
}

// ---------------------------------------------------------------------------
__global__ void k_count(const int* __restrict__ src, const int* __restrict__ dst,
                        int L) {
    int i = blockIdx.x * blockDim.x + threadIdx.x;
    if (i >= L) return;
    atomicAdd(&g_cnt[src[i]], 1);
    atomicAdd(&g_cnt[NNODES + dst[i]], 1);
}

// ---------------------------------------------------------------------------
// scanA: coalesced block-local exclusive scan (1024/block), per side.
// ---------------------------------------------------------------------------
__global__ void __launch_bounds__(1024)
k_scanA() {
    __shared__ int sh[1024];
    int side = blockIdx.y;
    int gid  = blockIdx.x * 1024 + threadIdx.x;
    int idx  = side * NNODES + gid;
    bool ok  = gid < NNODES;
    int c = ok ? g_cnt[idx] : 0;
    sh[threadIdx.x] = c;
    __syncthreads();
    for (int d = 1; d < 1024; d <<= 1) {
        int t = (threadIdx.x >= d) ? sh[threadIdx.x - d] : 0;
        __syncthreads();
        sh[threadIdx.x] += t;
        __syncthreads();
    }
    if (ok) {
        g_off [idx] = sh[threadIdx.x] - c;   // exclusive within block
        g_cnt2[idx] = c;
        g_inv [idx] = 1.0f / (float)max(c, 1);
        g_cur [idx] = 0;
        g_cnt [idx] = 0;                     // self-clean for next replay
    }
    if (threadIdx.x == 1023) g_bsum[side * SBLK + blockIdx.x] = sh[1023];
}

// scanB: one block scans the 98 block sums of each side (exclusive).
__global__ void k_scanB() {
    __shared__ int sh[2][128];
    int tid  = threadIdx.x;          // 256 threads
    int side = tid >> 7, j = tid & 127;
    int v = (j < SBLK) ? g_bsum[side * SBLK + j] : 0;
    sh[side][j] = v;
    __syncthreads();
    for (int d = 1; d < 128; d <<= 1) {
        int t = (j >= d) ? sh[side][j - d] : 0;
        __syncthreads();
        sh[side][j] += t;
        __syncthreads();
    }
    if (j < SBLK) g_boff[side * SBLK + j] = sh[side][j] - v;
}

// scanC: add block offsets (coalesced) + emit packed per-slot header.
__global__ void __launch_bounds__(1024)
k_scanC() {
    int side = blockIdx.y;
    int gid  = blockIdx.x * 1024 + threadIdx.x;
    if (gid >= NNODES) return;
    int idx = side * NNODES + gid;
    int off = g_off[idx] + g_boff[side * SBLK + blockIdx.x];
    g_off[idx] = off;
    g_hdr[idx] = make_float4(__int_as_float(off), __int_as_float(g_cnt2[idx]),
                             g_inv[idx], 0.0f);
}

// ---------------------------------------------------------------------------
// counting-sort fill: write fully-precomputed records at sorted positions.
// ---------------------------------------------------------------------------
__global__ void k_fill(const int* __restrict__ type, const int* __restrict__ src,
                       const float* __restrict__ sm, const int* __restrict__ dst,
                       const float* __restrict__ dm, const float* __restrict__ em,
                       const float* __restrict__ ts, const float* __restrict__ lu,
                       int L) {
    int i = blockIdx.x * blockDim.x + threadIdx.x;
    if (i >= L) return;
    int   s   = src[i], d = dst[i];
    float smv = sm[i], dmv = dm[i], emv = em[i], t = ts[i];
    float ty  = (float)type[i];
    float lus = __ldg(lu + s), lud = __ldg(lu + d);

    // src side: message scale cb = event_mask
    int p = atomicAdd(&g_cur[s], 1) + g_off[s];
    g_rec[2 * p]     = make_float4(__int_as_float(i), __int_as_float(d),
                                   ty * emv, smv * emv);
    g_rec[2 * p + 1] = make_float4(dmv * emv, emv, t - lus * dmv, 0.0f);

    // dst side: cb = dst_mask (faithful: lu*dst_mask both sides)
    p = atomicAdd(&g_cur[NNODES + d], 1) + g_off[NNODES + d] + LMAX;
    g_rec[2 * p]     = make_float4(__int_as_float(i), __int_as_float(s),
                                   ty * dmv, dmv * dmv);
    g_rec[2 * p + 1] = make_float4(smv * dmv, dmv, t - lud * dmv, 0.0f);
}

// ---------------------------------------------------------------------------
// gather: one warp per (side,node), lane l owns h = 4l..4l+3 (float4 rows).
// 2-record unroll: 4 independent gathers + 4 prefetch loads in flight per
// iteration, single accumulator set (low regs -> high occupancy).
// ---------------------------------------------------------------------------
__global__ void __launch_bounds__(256)
k_gather(const float4* __restrict__ E4, const float4* __restrict__ M4,
         const float4* __restrict__ W4, const float4* __restrict__ B4,
         float4* __restrict__ out4) {
    int gw   = (blockIdx.x * blockDim.x + threadIdx.x) >> 5;
    int lane = threadIdx.x & 31;
    if (gw >= 2 * NNODES) return;
    int  slot  = gw;
    bool dside = slot >= NNODES;
    int  n     = dside ? slot - NNODES : slot;

    float4 hdr = __ldg(&g_hdr[slot]);
    int   off  = __float_as_int(hdr.x) + (dside ? LMAX : 0);
    int   cnt  = __float_as_int(hdr.y);
    float inv  = hdr.z;
    float4 wv = __ldg(W4 + lane), bv = __ldg(B4 + lane);

    float  a0 = 0.f, a1 = 0.f;
    float4 a2 = make_float4(0, 0, 0, 0);
    float4 a3 = make_float4(0, 0, 0, 0);
    float4 a4 = make_float4(0, 0, 0, 0);

    // pipeline: hold records j (r0) and j+1 (r1)
    float4 ra0 = make_float4(0,0,0,0), rb0 = ra0, ra1 = ra0, rb1 = ra0;
    if (cnt > 0) { ra0 = __ldg(g_rec + 2*off);     rb0 = __ldg(g_rec + 2*off + 1); }
    if (cnt > 1) { ra1 = __ldg(g_rec + 2*off + 2); rb1 = __ldg(g_rec + 2*off + 3); }

    for (int j = 0; j < cnt; j += 2) {
        // prefetch records j+2, j+3
        float4 ra0n = ra0, rb0n = rb0, ra1n = ra1, rb1n = rb1;
        if (j + 2 < cnt) {
            ra0n = __ldg(g_rec + 2*(off + j + 2));
            rb0n = __ldg(g_rec + 2*(off + j + 2) + 1);
        }
        if (j + 3 < cnt) {
            ra1n = __ldg(g_rec + 2*(off + j + 3));
            rb1n = __ldg(g_rec + 2*(off + j + 3) + 1);
        }
        // issue all gathers before any math
        bool p1 = (j + 1 < cnt);
        float4 Ev0 = __ldcs(E4 + (size_t)__float_as_int(ra0.x) * 32 + lane);
        float4 Mv0 = __ldg (M4 + (size_t)__float_as_int(ra0.y) * 32 + lane);
        float4 Ev1, Mv1;
        if (p1) {
            Ev1 = __ldcs(E4 + (size_t)__float_as_int(ra1.x) * 32 + lane);
            Mv1 = __ldg (M4 + (size_t)__float_as_int(ra1.y) * 32 + lane);
        }
        // math for record j
        {
            float cm = rb0.x, cb = rb0.y, x = rb0.z;
            a0 += ra0.z;  a1 += ra0.w;
            a2.x = fmaf(Mv0.x, cm, a2.x); a2.y = fmaf(Mv0.y, cm, a2.y);
            a2.z = fmaf(Mv0.z, cm, a2.z); a2.w = fmaf(Mv0.w, cm, a2.w);
            a3.x = fmaf(fast_cos(fmaf(x, wv.x, bv.x)), cb, a3.x);
            a3.y = fmaf(fast_cos(fmaf(x, wv.y, bv.y)), cb, a3.y);
            a3.z = fmaf(fast_cos(fmaf(x, wv.z, bv.z)), cb, a3.z);
            a3.w = fmaf(fast_cos(fmaf(x, wv.w, bv.w)), cb, a3.w);
            a4.x = fmaf(Ev0.x, cb, a4.x); a4.y = fmaf(Ev0.y, cb, a4.y);
            a4.z = fmaf(Ev0.z, cb, a4.z); a4.w = fmaf(Ev0.w, cb, a4.w);
        }
        // math for record j+1
        if (p1) {
            float cm = rb1.x, cb = rb1.y, x = rb1.z;
            a0 += ra1.z;  a1 += ra1.w;
            a2.x = fmaf(Mv1.x, cm, a2.x); a2.y = fmaf(Mv1.y, cm, a2.y);
            a2.z = fmaf(Mv1.z, cm, a2.z); a2.w = fmaf(Mv1.w, cm, a2.w);
            a3.x = fmaf(fast_cos(fmaf(x, wv.x, bv.x)), cb, a3.x);
            a3.y = fmaf(fast_cos(fmaf(x, wv.y, bv.y)), cb, a3.y);
            a3.z = fmaf(fast_cos(fmaf(x, wv.z, bv.z)), cb, a3.z);
            a3.w = fmaf(fast_cos(fmaf(x, wv.w, bv.w)), cb, a3.w);
            a4.x = fmaf(Ev1.x, cb, a4.x); a4.y = fmaf(Ev1.y, cb, a4.y);
            a4.z = fmaf(Ev1.z, cb, a4.z); a4.w = fmaf(Ev1.w, cb, a4.w);
        }
        ra0 = ra0n; rb0 = rb0n; ra1 = ra1n; rb1 = rb1n;
    }

    float4 Mn = __ldg(M4 + (size_t)n * 32 + lane);
    float  b0 = a0 * inv, b1 = a1 * inv;
    float4* o = out4 + (size_t)slot * 160;   // 640/4
    __stcs(o + lane,       make_float4(b0, b0, b0, b0));
    __stcs(o + 32 + lane,  make_float4(Mn.x * b1, Mn.y * b1, Mn.z * b1, Mn.w * b1));
    __stcs(o + 64 + lane,  make_float4(a2.x * inv, a2.y * inv, a2.z * inv, a2.w * inv));
    __stcs(o + 96 + lane,  make_float4(a3.x * inv, a3.y * inv, a3.z * inv, a3.w * inv));
    __stcs(o + 128 + lane, make_float4(a4.x * inv, a4.y * inv, a4.z * inv, a4.w * inv));
}

// ---------------------------------------------------------------------------
extern "C" void kernel_launch(void* const* d_in, const int* in_sizes, int n_in,
                              void* d_out, int out_size) {
    const int*   type = (const int*)  d_in[0];
    const int*   src  = (const int*)  d_in[1];
    const float* smk  = (const float*)d_in[2];
    const int*   dst  = (const int*)  d_in[3];
    const float* dmk  = (const float*)d_in[4];
    const float* E    = (const float*)d_in[5];
    const float* em   = (const float*)d_in[6];
    const float* ts   = (const float*)d_in[7];
    const float* mem  = (const float*)d_in[8];
    const float* lu   = (const float*)d_in[9];
    const float* w    = (const float*)d_in[10];
    const float* b    = (const float*)d_in[11];
    float* out = (float*)d_out;
    int L = in_sizes[0];
    if (L > LMAX) L = LMAX;

    dim3 sgrid(SBLK, 2);
    k_count<<<(L + 255) / 256, 256>>>(src, dst, L);
    k_scanA<<<sgrid, 1024>>>();
    k_scanB<<<1, 256>>>();
    k_scanC<<<sgrid, 1024>>>();
    k_fill <<<(L + 255) / 256, 256>>>(type, src, smk, dst, dmk, em, ts, lu, L);

    int warps = 2 * NNODES;
    k_gather<<<(warps * 32 + 255) / 256, 256>>>(
        (const float4*)E, (const float4*)mem, (const float4*)w,
        (const float4*)b, (float4*)out);
}

// round 17
// speedup vs baseline: 1.1276x; 1.0645x over previous
#include <cuda_runtime.h>
#include <cuda_bf16.h>
#include <cstdint>

#define NNODES 100000
#define HD 128
#define ROW 640      // 5*HD
#define LMAX 262144
#define SBLK 98      // ceil(100000/1024) scan blocks per side

// scratch (self-cleaning across graph replays; zero-init at load)
__device__ int    g_cnt [2 * NNODES];  // k_count +, scanA reads then zeroes
__device__ int    g_cnt2[2 * NNODES];  // snapshot (scanA)
__device__ int    g_off [2 * NNODES];
__device__ int    g_cur [2 * NNODES];
__device__ float  g_inv [2 * NNODES];
__device__ float4 g_hdr [2 * NNODES];  // {bits(off), bits(cnt), inv, 0} (scanC)
__device__ int    g_bsum[2 * SBLK];
__device__ int    g_boff[2 * SBLK];
// sorted per-(side,position) event records: 2 float4s each.
// rec[2p+0] = {bits(e), bits(other), s0, c1}   rec[2p+1] = {cm, cb, x, pad}
__device__ float4 g_rec[4 * LMAX];

// ---------------------------------------------------------------------------
// fast cos: Cody-Waite FMA reduction + cephes minimax polys. |x|<=~1000 here.
// ---------------------------------------------------------------------------
__device__ __forceinline__ float fast_cos(float x) {
    float j = rintf(x * 0.63661977236758134f);
    int   q = (int)j;
    float r = fmaf(j, -1.5707963705062866f, x);
    r = fmaf(j, 4.3711390e-8f, r);
    float r2 = r * r;
    float ps = fmaf(r2, -1.9515295891e-4f, 8.3321608736e-3f);
    ps = fmaf(r2, ps, -1.6666654611e-1f);
    float s  = fmaf(r * r2, ps, r);
    float pc = fmaf(r2, 2.443315711809948e-5f, -1.388731625493765e-3f);
    pc = fmaf(r2, pc, 4.166664568298827e-2f);
    pc = fmaf(r2, pc, -0.5f);
    float c  = fmaf(r2, pc, 1.0f);
    float v = (q & 1) ? s : c;
    if ((q + 1) & 2) v = -v;
    return v;
}

// ---------------------------------------------------------------------------
__global__ void k_count(const int* __restrict__ src, const int* __restrict__ dst,
                        int L) {
    int i = blockIdx.x * blockDim.x + threadIdx.x;
    if (i >= L) return;
    atomicAdd(&g_cnt[src[i]], 1);
    atomicAdd(&g_cnt[NNODES + dst[i]], 1);
}

// ---------------------------------------------------------------------------
// scanA: coalesced block-local exclusive scan (1024/block), per side.
// ---------------------------------------------------------------------------
__global__ void __launch_bounds__(1024)
k_scanA() {
    __shared__ int sh[1024];
    int side = blockIdx.y;
    int gid  = blockIdx.x * 1024 + threadIdx.x;
    int idx  = side * NNODES + gid;
    bool ok  = gid < NNODES;
    int c = ok ? g_cnt[idx] : 0;
    sh[threadIdx.x] = c;
    __syncthreads();
    for (int d = 1; d < 1024; d <<= 1) {
        int t = (threadIdx.x >= d) ? sh[threadIdx.x - d] : 0;
        __syncthreads();
        sh[threadIdx.x] += t;
        __syncthreads();
    }
    if (ok) {
        g_off [idx] = sh[threadIdx.x] - c;   // exclusive within block
        g_cnt2[idx] = c;
        g_inv [idx] = 1.0f / (float)max(c, 1);
        g_cur [idx] = 0;
        g_cnt [idx] = 0;                     // self-clean for next replay
    }
    if (threadIdx.x == 1023) g_bsum[side * SBLK + blockIdx.x] = sh[1023];
}

// scanB: one block scans the 98 block sums of each side (exclusive).
__global__ void k_scanB() {
    __shared__ int sh[2][128];
    int tid  = threadIdx.x;          // 256 threads
    int side = tid >> 7, j = tid & 127;
    int v = (j < SBLK) ? g_bsum[side * SBLK + j] : 0;
    sh[side][j] = v;
    __syncthreads();
    for (int d = 1; d < 128; d <<= 1) {
        int t = (j >= d) ? sh[side][j - d] : 0;
        __syncthreads();
        sh[side][j] += t;
        __syncthreads();
    }
    if (j < SBLK) g_boff[side * SBLK + j] = sh[side][j] - v;
}

// scanC: add block offsets (coalesced) + emit packed per-slot header.
__global__ void __launch_bounds__(1024)
k_scanC() {
    int side = blockIdx.y;
    int gid  = blockIdx.x * 1024 + threadIdx.x;
    if (gid >= NNODES) return;
    int idx = side * NNODES + gid;
    int off = g_off[idx] + g_boff[side * SBLK + blockIdx.x];
    g_off[idx] = off;
    g_hdr[idx] = make_float4(__int_as_float(off), __int_as_float(g_cnt2[idx]),
                             g_inv[idx], 0.0f);
}

// ---------------------------------------------------------------------------
// counting-sort fill: write fully-precomputed records at sorted positions.
// ---------------------------------------------------------------------------
__global__ void k_fill(const int* __restrict__ type, const int* __restrict__ src,
                       const float* __restrict__ sm, const int* __restrict__ dst,
                       const float* __restrict__ dm, const float* __restrict__ em,
                       const float* __restrict__ ts, const float* __restrict__ lu,
                       int L) {
    int i = blockIdx.x * blockDim.x + threadIdx.x;
    if (i >= L) return;
    int   s   = src[i], d = dst[i];
    float smv = sm[i], dmv = dm[i], emv = em[i], t = ts[i];
    float ty  = (float)type[i];
    float lus = __ldg(lu + s), lud = __ldg(lu + d);

    // src side: message scale cb = event_mask
    int p = atomicAdd(&g_cur[s], 1) + g_off[s];
    g_rec[2 * p]     = make_float4(__int_as_float(i), __int_as_float(d),
                                   ty * emv, smv * emv);
    g_rec[2 * p + 1] = make_float4(dmv * emv, emv, t - lus * dmv, 0.0f);

    // dst side: cb = dst_mask (faithful: lu*dst_mask both sides)
    p = atomicAdd(&g_cur[NNODES + d], 1) + g_off[NNODES + d] + LMAX;
    g_rec[2 * p]     = make_float4(__int_as_float(i), __int_as_float(s),
                                   ty * dmv, dmv * dmv);
    g_rec[2 * p + 1] = make_float4(smv * dmv, dmv, t - lud * dmv, 0.0f);
}

// ---------------------------------------------------------------------------
// gather: TWO warps per (side,node); warp half h covers float2 elements
// [32h, 32h+32) of every 128-float block. Single-record pipelined loop
// (the R14 structure that measured best); minimal per-warp state.
// ---------------------------------------------------------------------------
__global__ void __launch_bounds__(256)
k_gather(const float2* __restrict__ E2, const float2* __restrict__ M2,
         const float2* __restrict__ W2, const float2* __restrict__ B2,
         float2* __restrict__ out2) {
    int gw   = (blockIdx.x * blockDim.x + threadIdx.x) >> 5;
    int lane = threadIdx.x & 31;
    if (gw >= 4 * NNODES) return;
    int  slot  = gw >> 1;
    int  idx   = ((gw & 1) << 5) + lane;    // float2 index 0..63 within block
    bool dside = slot >= NNODES;
    int  n     = dside ? slot - NNODES : slot;

    float4 hdr = __ldg(&g_hdr[slot]);
    int   off  = __float_as_int(hdr.x) + (dside ? LMAX : 0);
    int   cnt  = __float_as_int(hdr.y);
    float inv  = hdr.z;
    float2 wv = __ldg(W2 + idx), bv = __ldg(B2 + idx);

    float  a0 = 0.f, a1 = 0.f;
    float2 a2 = make_float2(0, 0);
    float2 a3 = make_float2(0, 0);
    float2 a4 = make_float2(0, 0);

    float4 ra = make_float4(0, 0, 0, 0), rb = ra;
    if (cnt > 0) { ra = __ldg(g_rec + 2 * off); rb = __ldg(g_rec + 2 * off + 1); }
    for (int j = 0; j < cnt; j++) {
        float4 ra_n = ra, rb_n = rb;
        if (j + 1 < cnt) {
            ra_n = __ldg(g_rec + 2 * (off + j + 1));
            rb_n = __ldg(g_rec + 2 * (off + j + 1) + 1);
        }
        int   e     = __float_as_int(ra.x);
        int   other = __float_as_int(ra.y);
        float cm = rb.x, cb = rb.y, x = rb.z;
        float2 Ev = __ldcs(E2 + (size_t)e * 64 + idx);      // streamed
        float2 Mv = __ldg (M2 + (size_t)other * 64 + idx);  // L2-resident
        a0 += ra.z;
        a1 += ra.w;
        a2.x = fmaf(Mv.x, cm, a2.x); a2.y = fmaf(Mv.y, cm, a2.y);
        a3.x = fmaf(fast_cos(fmaf(x, wv.x, bv.x)), cb, a3.x);
        a3.y = fmaf(fast_cos(fmaf(x, wv.y, bv.y)), cb, a3.y);
        a4.x = fmaf(Ev.x, cb, a4.x); a4.y = fmaf(Ev.y, cb, a4.y);
        ra = ra_n; rb = rb_n;
    }

    float2 Mn = __ldg(M2 + (size_t)n * 64 + idx);
    float  b0 = a0 * inv, b1 = a1 * inv;
    float2* o = out2 + (size_t)slot * 320;   // 640/2
    __stcs(o + idx,        make_float2(b0, b0));
    __stcs(o + 64 + idx,   make_float2(Mn.x * b1, Mn.y * b1));
    __stcs(o + 128 + idx,  make_float2(a2.x * inv, a2.y * inv));
    __stcs(o + 192 + idx,  make_float2(a3.x * inv, a3.y * inv));
    __stcs(o + 256 + idx,  make_float2(a4.x * inv, a4.y * inv));
}

// ---------------------------------------------------------------------------
extern "C" void kernel_launch(void* const* d_in, const int* in_sizes, int n_in,
                              void* d_out, int out_size) {
    const int*   type = (const int*)  d_in[0];
    const int*   src  = (const int*)  d_in[1];
    const float* smk  = (const float*)d_in[2];
    const int*   dst  = (const int*)  d_in[3];
    const float* dmk  = (const float*)d_in[4];
    const float* E    = (const float*)d_in[5];
    const float* em   = (const float*)d_in[6];
    const float* ts   = (const float*)d_in[7];
    const float* mem  = (const float*)d_in[8];
    const float* lu   = (const float*)d_in[9];
    const float* w    = (const float*)d_in[10];
    const float* b    = (const float*)d_in[11];
    float* out = (float*)d_out;
    int L = in_sizes[0];
    if (L > LMAX) L = LMAX;

    dim3 sgrid(SBLK, 2);
    k_count<<<(L + 255) / 256, 256>>>(src, dst, L);
    k_scanA<<<sgrid, 1024>>>();
    k_scanB<<<1, 256>>>();
    k_scanC<<<sgrid, 1024>>>();
    k_fill <<<(L + 255) / 256, 256>>>(type, src, smk, dst, dmk, em, ts, lu, L);

    int warps = 4 * NNODES;   // two warps per slot
    k_gather<<<(warps * 32 + 255) / 256, 256>>>(
        (const float2*)E, (const float2*)mem, (const float2*)w,
        (const float2*)b, (float2*)out);
}